// round 10
// baseline (speedup 1.0000x reference)
#include <cuda_runtime.h>
#include <cstdint>

#define BB 256
#define TT 256
#define CC 1024
#define LL 64
#define SS 129          // 2L+1
#define GW 80           // gather width: 64 labels + blank@64 + zero pad to 80
#define CH 8            // time-rows per chunk (sync + smem granularity)
#define NCHUNK (TT / CH)                // 32
#define CBLK 64                         // consumer blocks (4 batches each)
#define PBLK ((BB * TT) / 8)            // 8192 producer blocks, 8 rows each
#define EPSF 1e-7f
#define LN2F 0.69314718055994530942f

// scratch (no allocation allowed -> __device__ globals)
__device__ float g_buf[(size_t)BB * TT * GW];   // emit table, LINEAR domain
__device__ int   done_ctr[NCHUNK];              // rows completed per t-chunk

__device__ __forceinline__ float flog2(float x) {
    float y; asm("lg2.approx.ftz.f32 %0, %1;" : "=f"(y) : "f"(x)); return y;
}
__device__ __forceinline__ bool detect_i64(const int* yt, int lane) {
    return __all_sync(0xffffffffu, yt[2 * lane + 1] == 0);
}
__device__ __forceinline__ int load_lab(const int* yt, bool is64, int idx) {
    int v = is64 ? yt[2 * idx] : yt[idx];
    return min(max(v, 0), CC - 1);              // clamp: safety net
}

__global__ void k_zero() { if (threadIdx.x < NCHUNK) done_ctr[threadIdx.x] = 0; }

// ---------------------------------------------------------------------------
// producer warp: ONE (b,t) row (identical shape to the proven 43us reduce
// kernel -- one-shot warps keep full MLP).  Rows indexed t-major so early
// time chunks of all batches finish first.
// softmax(log(y+EPS)) = (y+EPS)/sum(y+EPS): one plain sum + divide.
// ---------------------------------------------------------------------------
__device__ __forceinline__ void produce_row(const float* __restrict__ yp,
                                            const int*   __restrict__ yt,
                                            int r, int lane, bool is64) {
    int t = r >> 8;                             // t-major
    int b = r & (BB - 1);

    const float*  row  = yp + ((size_t)b * TT + t) * CC;
    const float4* row4 = (const float4*)row;

    float s = 0.f;
    #pragma unroll
    for (int k = 0; k < 8; ++k) {               // 8 coalesced float4 per lane
        float4 v = row4[lane + 32 * k];
        s += (v.x + v.y) + (v.z + v.w);
    }
    #pragma unroll
    for (int o = 16; o; o >>= 1) s += __shfl_xor_sync(0xffffffffu, s, o);

    float invZ = 1.0f / (s + (float)CC * EPSF);

    float* go = g_buf + ((size_t)b * TT + t) * GW;
    #pragma unroll
    for (int q = 0; q < 2; ++q) {
        int j   = lane + 32 * q;
        int lab = load_lab(yt, is64, b * LL + j);
        go[j]   = (row[lab] + EPSF) * invZ;          // L1 hit: row just read
    }
    if (lane == 0)      go[64] = (row[CC - 1] + EPSF) * invZ;   // blank
    else if (lane < 16) go[64 + lane] = 0.0f;                   // zero pad

    __syncwarp();                                // lanes' stores ordered
    __threadfence();                             // release
    if (lane == 0) atomicAdd(&done_ctr[t >> 3], 1);
}

// ---------------------------------------------------------------------------
// consumer: alpha recursion, LINEAR domain a_new = (a1+a2+skip*a3)*p, pure
// FMA pipe.  One warp per batch, 5 states/thread, 2 shuffles/step.  cp.async
// double-buffered smem chunks; spin-wait (acquire) on done_ctr before each.
// Renorm by warp-max exponent every 8 steps via redux.sync (1 op).
// ---------------------------------------------------------------------------
__device__ __forceinline__ void wait_ready(int c, int lane) {
    if (lane == 0) {
        volatile int* p = &done_ctr[c];
        while (*p < CH * BB) __nanosleep(64);
    }
    __syncwarp();
    __threadfence();                             // acquire
}
__device__ __forceinline__ void issue_chunk(const float4* gsrc,
                                            unsigned int sdst, int lane) {
    #pragma unroll
    for (int k = 0; k < (CH * GW) / (4 * 32); ++k) {   // 5 iters
        int i4 = lane + 32 * k;
        asm volatile("cp.async.ca.shared.global [%0], [%1], 16;\n"
                     :: "r"(sdst + 16u * i4), "l"(gsrc + i4));
    }
    asm volatile("cp.async.commit_group;\n" ::: "memory");
}
__device__ __forceinline__ void wait_cp() {
    asm volatile("cp.async.wait_group 0;\n" ::: "memory");
    __syncwarp();
}

__global__ void k_fused(const float* __restrict__ yp,
                        const int*   __restrict__ yt,
                        float* __restrict__ out) {
    __shared__ __align__(16) float sm[4][2][CH * GW];  // 20,480 B

    int w    = threadIdx.x >> 5;
    int lane = threadIdx.x & 31;
    bool is64 = detect_i64(yt, lane);

    if (blockIdx.x >= CBLK) {                   // ---------- producer role
        produce_row(yp, yt, (blockIdx.x - CBLK) * 8 + w, lane, is64);
        return;
    }
    if (w >= 4) return;                         // consumer: warps 0-3 only

    // ---------- consumer role: batch b per warp
    int b = blockIdx.x * 4 + w;

    int   eidx[5];
    float skipm[5];
    #pragma unroll
    for (int i = 0; i < 5; ++i) {
        int s    = 5 * lane + i;
        bool odd = (s & 1);
        eidx[i]  = (s < SS) ? (odd ? ((s - 1) >> 1) : 64) : 66;  // 66 -> p=0
        skipm[i] = 0.0f;
        if (s < SS && odd && s >= 3) {          // pos>=2 and label state
            int j = (s - 1) >> 1;               // j >= 1 here
            skipm[i] = (load_lab(yt, is64, b * LL + j) !=
                        load_lab(yt, is64, b * LL + j - 1)) ? 1.0f : 0.0f;
        }
    }

    const float4* gb4 = (const float4*)(g_buf + (size_t)b * TT * GW);
    unsigned int sbase[2] = {
        (unsigned int)__cvta_generic_to_shared(&sm[w][0][0]),
        (unsigned int)__cvta_generic_to_shared(&sm[w][1][0])
    };

    wait_ready(0, lane);
    issue_chunk(gb4, sbase[0], lane);
    wait_cp();

    float a[5];
    {   // t = 0 init: only states 0,1 live
        const float* s0 = &sm[w][0][0];
        #pragma unroll
        for (int i = 0; i < 5; ++i) {
            int s = 5 * lane + i;
            a[i]  = (s < 2) ? s0[eidx[i]] : 0.0f;
        }
    }
    float acc = 0.0f;                           // accumulated log2 scale

    #pragma unroll 1
    for (int c = 0; c < NCHUNK; ++c) {
        if (c + 1 < NCHUNK) {                   // stream next chunk while computing
            wait_ready(c + 1, lane);
            issue_chunk(gb4 + (size_t)(c + 1) * (CH * GW / 4),
                        sbase[(c + 1) & 1], lane);
        }

        const float* sbuf = &sm[w][c & 1][0];

        #pragma unroll
        for (int r = 0; r < CH; ++r) {
            if (c == 0 && r == 0) continue;     // t=0 consumed by init
            const float* srow = sbuf + r * GW;
            float p[5];
            #pragma unroll
            for (int i = 0; i < 5; ++i) p[i] = srow[eidx[i]];

            float q4 = __shfl_up_sync(0xffffffffu, a[4], 1);   // state 5*lane-1
            float q3 = __shfl_up_sync(0xffffffffu, a[3], 1);   // state 5*lane-2
            if (lane == 0) { q4 = 0.0f; q3 = 0.0f; }

            float n0 = (a[0] + q4   + skipm[0] * q3  ) * p[0];
            float n1 = (a[1] + a[0] + skipm[1] * q4  ) * p[1];
            float n2 = (a[2] + a[1] + skipm[2] * a[0]) * p[2];
            float n3 = (a[3] + a[2] + skipm[3] * a[1]) * p[3];
            float n4 = (a[4] + a[3] + skipm[4] * a[2]) * p[4];
            a[0] = n0; a[1] = n1; a[2] = n2; a[3] = n3; a[4] = n4;

            if (r == CH - 1) {                  // renorm every 8 steps
                float m = fmaxf(fmaxf(fmaxf(a[0], a[1]), fmaxf(a[2], a[3])), a[4]);
                unsigned int mu = __float_as_uint(m);   // positive: order-safe
                asm("redux.sync.max.u32 %0, %1, 0xffffffff;" : "=r"(mu) : "r"(mu));
                int ebits = (int)((mu >> 23) & 0xFFu);
                float scale = __int_as_float((254 - ebits) << 23);  // 2^-(e-127)
                acc += (float)(ebits - 127);
                #pragma unroll
                for (int i = 0; i < 5; ++i) a[i] *= scale;
            }
        }

        if (c + 1 < NCHUNK) wait_cp();          // next buffer ready
    }

    // states 127 (i=2) and 128 (i=3) live in lane 25
    if (lane == 25) {
        float s = a[2] + a[3];                  // tail sum, linear
        out[b] = -(flog2(s) + acc) * LN2F;
    }
}

// ---------------------------------------------------------------------------
extern "C" void kernel_launch(void* const* d_in, const int* in_sizes, int n_in,
                              void* d_out, int out_size) {
    // y_pred is by far the larger buffer; robust to metadata ordering.
    const float* yp;
    const int*   yt;
    if (in_sizes[0] > in_sizes[1]) {
        yp = (const float*)d_in[0];
        yt = (const int*)d_in[1];
    } else {
        yp = (const float*)d_in[1];
        yt = (const int*)d_in[0];
    }
    float* out = (float*)d_out;

    k_zero<<<1, 32>>>();                        // reset chunk counters
    k_fused<<<CBLK + PBLK, 256>>>(yp, yt, out); // consumers first, then producers
}

// round 11
// speedup vs baseline: 1.3344x; 1.3344x over previous
#include <cuda_runtime.h>
#include <cstdint>

#define BB 256
#define TT 256
#define CC 1024
#define LL 64
#define SS 129          // 2L+1
#define GW 144          // state-major emit width: states 0..128 + zero pad
#define CH 8            // time-rows per smem chunk
#define NCHUNK (TT / CH)                // 32
#define EPSF 1e-7f
#define LN2F 0.69314718055994530942f

// scratch (no allocation allowed -> __device__ global); 16B aligned for float4
__device__ __align__(16) float g_buf[(size_t)BB * TT * GW];

__device__ __forceinline__ float flog2(float x) {
    float y; asm("lg2.approx.ftz.f32 %0, %1;" : "=f"(y) : "f"(x)); return y;
}
__device__ __forceinline__ bool detect_i64(const int* yt, int lane) {
    return __all_sync(0xffffffffu, yt[2 * lane + 1] == 0);
}
__device__ __forceinline__ int load_lab(const int* yt, bool is64, int idx) {
    int v = is64 ? yt[2 * idx] : yt[idx];
    return min(max(v, 0), CC - 1);              // clamp: safety net
}

// ---------------------------------------------------------------------------
// Kernel 1: per (b,t) row, one warp each (b-major: proven 5.8 TB/s shape).
// softmax(log(y+EPS)) = (y+EPS)/sum(y+EPS): one plain sum + divide.
// Emits STATE-MAJOR linear probs: g[b][t][s], even s = blank, odd s = label.
// ---------------------------------------------------------------------------
__global__ void k_reduce_gather(const float* __restrict__ yp,
                                const int*   __restrict__ yt) {
    int warp = (blockIdx.x * blockDim.x + threadIdx.x) >> 5;
    int lane = threadIdx.x & 31;
    if (warp >= BB * TT) return;
    int b = warp >> 8;                          // row-major (B,T,C)

    bool is64 = detect_i64(yt, lane);

    const float*  row  = yp + (size_t)warp * CC;
    const float4* row4 = (const float4*)row;

    float s = 0.f;
    #pragma unroll
    for (int k = 0; k < 8; ++k) {               // 8 coalesced float4 per lane
        float4 v = row4[lane + 32 * k];
        s += (v.x + v.y) + (v.z + v.w);
    }
    #pragma unroll
    for (int o = 16; o; o >>= 1) s += __shfl_xor_sync(0xffffffffu, s, o);

    float invZ  = 1.0f / (s + (float)CC * EPSF);
    float blank = (row[CC - 1] + EPSF) * invZ;

    int lab0 = load_lab(yt, is64, b * LL + 2 * lane);
    int lab1 = load_lab(yt, is64, b * LL + 2 * lane + 1);
    float v0 = (row[lab0] + EPSF) * invZ;       // L1 hits: row just read
    float v1 = (row[lab1] + EPSF) * invZ;

    float4* go4 = (float4*)(g_buf + (size_t)warp * GW);
    // lane l covers states 4l..4l+3 = {blank, lab[2l], blank, lab[2l+1]}
    go4[lane] = make_float4(blank, v0, blank, v1);
    if (lane < 4)                               // states 128..143
        go4[32 + lane] = (lane == 0) ? make_float4(blank, 0.f, 0.f, 0.f)
                                     : make_float4(0.f, 0.f, 0.f, 0.f);
}

// ---------------------------------------------------------------------------
// Kernel 2: alpha recursion, LINEAR domain: a_new = (a1 + a2 + skip*a3) * p.
// One warp per batch, 5 contiguous states/thread (conflict-free stride-5 LDS,
// addresses precomputed), 2 shuffles/step, branch-free 8-step chunks with
// cp.async double buffering.  Renorm by warp-max exponent once per chunk.
// ---------------------------------------------------------------------------
__device__ __forceinline__ void issue_chunk(const float4* gsrc,
                                            unsigned int sdst, int lane) {
    #pragma unroll
    for (int k = 0; k < (CH * GW) / (4 * 32); ++k) {   // 9 iters
        int i4 = lane + 32 * k;
        asm volatile("cp.async.ca.shared.global [%0], [%1], 16;\n"
                     :: "r"(sdst + 16u * i4), "l"(gsrc + i4));
    }
    asm volatile("cp.async.commit_group;\n" ::: "memory");
}
__device__ __forceinline__ void wait_cp() {
    asm volatile("cp.async.wait_group 0;\n" ::: "memory");
    __syncwarp();
}

__device__ __forceinline__ void step_row(const float* __restrict__ srow,
                                         const int* __restrict__ addr,
                                         const float* __restrict__ skipm,
                                         float* __restrict__ a, int lane) {
    float p[5];
    #pragma unroll
    for (int i = 0; i < 5; ++i) p[i] = srow[addr[i]];

    float q4 = __shfl_up_sync(0xffffffffu, a[4], 1);   // state 5*lane-1
    float q3 = __shfl_up_sync(0xffffffffu, a[3], 1);   // state 5*lane-2
    if (lane == 0) { q4 = 0.0f; q3 = 0.0f; }

    float n0 = (a[0] + q4   + skipm[0] * q3  ) * p[0];
    float n1 = (a[1] + a[0] + skipm[1] * q4  ) * p[1];
    float n2 = (a[2] + a[1] + skipm[2] * a[0]) * p[2];
    float n3 = (a[3] + a[2] + skipm[3] * a[1]) * p[3];
    float n4 = (a[4] + a[3] + skipm[4] * a[2]) * p[4];
    a[0] = n0; a[1] = n1; a[2] = n2; a[3] = n3; a[4] = n4;
}

__device__ __forceinline__ void renorm(float* __restrict__ a, float& acc) {
    float m = fmaxf(fmaxf(fmaxf(a[0], a[1]), fmaxf(a[2], a[3])), a[4]);
    unsigned int mu = __float_as_uint(m);       // positive floats: order-safe
    asm("redux.sync.max.u32 %0, %1, 0xffffffff;" : "=r"(mu) : "r"(mu));
    int ebits = (int)((mu >> 23) & 0xFFu);
    float scale = __int_as_float((254 - ebits) << 23);  // 2^-(e-127)
    acc += (float)(ebits - 127);
    #pragma unroll
    for (int i = 0; i < 5; ++i) a[i] *= scale;
}

__global__ void __launch_bounds__(128, 1)
k_alpha(const int* __restrict__ yt, float* __restrict__ out) {
    __shared__ __align__(16) float sm[4][2][CH * GW];  // 36,864 B

    int w    = threadIdx.x >> 5;
    int b    = blockIdx.x * 4 + w;
    int lane = threadIdx.x & 31;
    if (b >= BB) return;

    bool is64 = detect_i64(yt, lane);

    int   addr[5];
    float skipm[5];
    #pragma unroll
    for (int i = 0; i < 5; ++i) {
        int s    = 5 * lane + i;
        addr[i]  = min(s, 130);                 // s>=129 -> pad slot 130 (p=0)
        skipm[i] = 0.0f;
        if (s < SS && (s & 1) && s >= 3) {      // pos>=2 and label state
            int j = (s - 1) >> 1;               // j >= 1 here
            skipm[i] = (load_lab(yt, is64, b * LL + j) !=
                        load_lab(yt, is64, b * LL + j - 1)) ? 1.0f : 0.0f;
        }
    }

    const float4* gb4 = (const float4*)(g_buf + (size_t)b * TT * GW);
    unsigned int sbase[2] = {
        (unsigned int)__cvta_generic_to_shared(&sm[w][0][0]),
        (unsigned int)__cvta_generic_to_shared(&sm[w][1][0])
    };

    // ---- peeled chunk 0: init at t=0, then steps t=1..7, renorm
    issue_chunk(gb4, sbase[0], lane);
    wait_cp();
    issue_chunk(gb4 + (CH * GW / 4), sbase[1], lane);   // chunk 1 in flight

    float a[5];
    {
        const float* s0 = &sm[w][0][0];
        #pragma unroll
        for (int i = 0; i < 5; ++i) {
            int s = 5 * lane + i;
            a[i]  = (s < 2) ? s0[addr[i]] : 0.0f;
        }
    }
    float acc = 0.0f;                           // accumulated log2 scale
    {
        const float* sbuf = &sm[w][0][0];
        #pragma unroll
        for (int r = 1; r < CH; ++r)
            step_row(sbuf + r * GW, addr, skipm, a, lane);
        renorm(a, acc);
    }

    // ---- chunks 1..31, branch-free bodies
    #pragma unroll 1
    for (int c = 1; c < NCHUNK; ++c) {
        wait_cp();                              // chunk c data ready
        if (c + 1 < NCHUNK)                     // stream next while computing
            issue_chunk(gb4 + (size_t)(c + 1) * (CH * GW / 4),
                        sbase[(c + 1) & 1], lane);

        const float* sbuf = &sm[w][c & 1][0];
        #pragma unroll
        for (int r = 0; r < CH; ++r)
            step_row(sbuf + r * GW, addr, skipm, a, lane);
        renorm(a, acc);
    }

    // states 127 (i=2) and 128 (i=3) live in lane 25
    if (lane == 25) {
        float s = a[2] + a[3];                  // tail sum, linear
        out[b] = -(flog2(s) + acc) * LN2F;
    }
}

// ---------------------------------------------------------------------------
extern "C" void kernel_launch(void* const* d_in, const int* in_sizes, int n_in,
                              void* d_out, int out_size) {
    // y_pred is by far the larger buffer; robust to metadata ordering.
    const float* yp;
    const int*   yt;
    if (in_sizes[0] > in_sizes[1]) {
        yp = (const float*)d_in[0];
        yt = (const int*)d_in[1];
    } else {
        yp = (const float*)d_in[1];
        yt = (const int*)d_in[0];
    }
    float* out = (float*)d_out;

    k_reduce_gather<<<(BB * TT) / 8, 256>>>(yp, yt);   // one warp per (b,t) row
    k_alpha<<<BB / 4, 128>>>(yt, out);                 // one warp per batch
}

// round 12
// speedup vs baseline: 1.5406x; 1.1545x over previous
#include <cuda_runtime.h>
#include <cuda_fp16.h>
#include <cstdint>

#define BB 256
#define TT 256
#define CC 1024
#define LL 64
#define SS 129          // 2L+1
#define GW 80           // emit width (halves): 64 labels + blank@64 + pad
#define CH 16           // time-rows per chunk; 16*80*2B = 2560B = 5 f4/lane
#define NCHUNK (TT / CH)                // 16
#define NBUF 4                          // cp.async pipeline depth
#define EPSF 1e-7f
#define LN2F 0.69314718055994530942f
#define PSCALE 1048576.0f               // 2^20: lifts p into fp16 normal range

// scratch (no allocation allowed -> __device__ global)
__device__ __align__(16) __half g_buf[(size_t)BB * TT * GW];  // p * 2^20, fp16

__device__ __forceinline__ float flog2(float x) {
    float y; asm("lg2.approx.ftz.f32 %0, %1;" : "=f"(y) : "f"(x)); return y;
}
__device__ __forceinline__ bool detect_i64(const int* yt, int lane) {
    return __all_sync(0xffffffffu, yt[2 * lane + 1] == 0);
}
__device__ __forceinline__ int load_lab(const int* yt, bool is64, int idx) {
    int v = is64 ? yt[2 * idx] : yt[idx];
    return min(max(v, 0), CC - 1);              // clamp: safety net
}

// ---------------------------------------------------------------------------
// Kernel 1: per (b,t) row, one warp each (b-major: proven ~5.9 TB/s shape).
// softmax(log(y+EPS)) = (y+EPS)/sum(y+EPS): one plain sum + divide.
// Emits COMPACT fp16 probs scaled by 2^20: g[b][t][j], j<64 labels, j=64 blank.
// ---------------------------------------------------------------------------
__global__ void k_reduce_gather(const float* __restrict__ yp,
                                const int*   __restrict__ yt) {
    int warp = (blockIdx.x * blockDim.x + threadIdx.x) >> 5;
    int lane = threadIdx.x & 31;
    if (warp >= BB * TT) return;
    int b = warp >> 8;                          // row-major (B,T,C)

    bool is64 = detect_i64(yt, lane);

    const float*  row  = yp + (size_t)warp * CC;
    const float4* row4 = (const float4*)row;

    float s = 0.f;
    #pragma unroll
    for (int k = 0; k < 8; ++k) {               // 8 coalesced float4 per lane
        float4 v = row4[lane + 32 * k];
        s += (v.x + v.y) + (v.z + v.w);
    }
    #pragma unroll
    for (int o = 16; o; o >>= 1) s += __shfl_xor_sync(0xffffffffu, s, o);

    float invZ = PSCALE / (s + (float)CC * EPSF);   // fold 2^20 into divide

    int lab0 = load_lab(yt, is64, b * LL + 2 * lane);
    int lab1 = load_lab(yt, is64, b * LL + 2 * lane + 1);
    __half2 v01 = __floats2half2_rn((row[lab0] + EPSF) * invZ,
                                    (row[lab1] + EPSF) * invZ);

    __half2* go2 = (__half2*)(g_buf + (size_t)warp * GW);
    go2[lane] = v01;                            // labels 2*lane, 2*lane+1
    if (lane < 8) {                             // j = 64..79: blank + zero pad
        __half2 z = __floats2half2_rn(
            (lane == 0) ? (row[CC - 1] + EPSF) * invZ : 0.f, 0.f);
        go2[32 + lane] = z;
    }
}

// ---------------------------------------------------------------------------
// Kernel 2: alpha recursion, LINEAR domain: a_new = (a1 + a2 + skip*a3) * p.
// One warp per batch, 5 states/thread, 2 shuffles/step.  4-deep cp.async
// pipeline (3 chunks in flight) hides DRAM latency; renorm by warp-max
// exponent every 8 steps (redux.sync, pure bit ops).
// ---------------------------------------------------------------------------
__device__ __forceinline__ void issue_chunk(const float4* gsrc,
                                            unsigned int sdst, int lane) {
    #pragma unroll
    for (int k = 0; k < (CH * GW * 2) / (16 * 32); ++k) {   // 5 iters
        int i4 = lane + 32 * k;
        asm volatile("cp.async.ca.shared.global [%0], [%1], 16;\n"
                     :: "r"(sdst + 16u * i4), "l"(gsrc + i4));
    }
    asm volatile("cp.async.commit_group;\n" ::: "memory");
}
template <int N>
__device__ __forceinline__ void wait_cp() {
    asm volatile("cp.async.wait_group %0;\n" :: "n"(N) : "memory");
    __syncwarp();
}

__device__ __forceinline__ void step_row(const __half* __restrict__ srow,
                                         const int* __restrict__ eidx,
                                         const float* __restrict__ skipm,
                                         float* __restrict__ a, int lane) {
    float p[5];
    #pragma unroll
    for (int i = 0; i < 5; ++i) p[i] = __half2float(srow[eidx[i]]);

    float q4 = __shfl_up_sync(0xffffffffu, a[4], 1);   // state 5*lane-1
    float q3 = __shfl_up_sync(0xffffffffu, a[3], 1);   // state 5*lane-2
    if (lane == 0) { q4 = 0.0f; q3 = 0.0f; }

    float n0 = (a[0] + q4   + skipm[0] * q3  ) * p[0];
    float n1 = (a[1] + a[0] + skipm[1] * q4  ) * p[1];
    float n2 = (a[2] + a[1] + skipm[2] * a[0]) * p[2];
    float n3 = (a[3] + a[2] + skipm[3] * a[1]) * p[3];
    float n4 = (a[4] + a[3] + skipm[4] * a[2]) * p[4];
    a[0] = n0; a[1] = n1; a[2] = n2; a[3] = n3; a[4] = n4;
}

__device__ __forceinline__ void renorm(float* __restrict__ a, float& acc) {
    float m = fmaxf(fmaxf(fmaxf(a[0], a[1]), fmaxf(a[2], a[3])), a[4]);
    unsigned int mu = __float_as_uint(m);       // positive floats: order-safe
    asm("redux.sync.max.u32 %0, %1, 0xffffffff;" : "=r"(mu) : "r"(mu));
    int ebits = (int)((mu >> 23) & 0xFFu);
    float scale = __int_as_float((254 - ebits) << 23);  // 2^-(e-127)
    acc += (float)(ebits - 127);
    #pragma unroll
    for (int i = 0; i < 5; ++i) a[i] *= scale;
}

__global__ void __launch_bounds__(128, 1)
k_alpha(const int* __restrict__ yt, float* __restrict__ out) {
    __shared__ __align__(16) __half sm[4][NBUF][CH * GW];  // 40,960 B

    int w    = threadIdx.x >> 5;
    int b    = blockIdx.x * 4 + w;
    int lane = threadIdx.x & 31;
    if (b >= BB) return;

    bool is64 = detect_i64(yt, lane);

    int   eidx[5];
    float skipm[5];
    #pragma unroll
    for (int i = 0; i < 5; ++i) {
        int s    = 5 * lane + i;
        bool odd = (s & 1);
        eidx[i]  = (s < SS) ? (odd ? ((s - 1) >> 1) : 64) : 66;  // 66 -> p=0
        skipm[i] = 0.0f;
        if (s < SS && odd && s >= 3) {          // pos>=2 and label state
            int j = (s - 1) >> 1;               // j >= 1 here
            skipm[i] = (load_lab(yt, is64, b * LL + j) !=
                        load_lab(yt, is64, b * LL + j - 1)) ? 1.0f : 0.0f;
        }
    }

    const float4* gb4 = (const float4*)(g_buf + (size_t)b * TT * GW);
    const int C4 = (CH * GW * 2) / 16;          // float4 per chunk = 160
    unsigned int sb[NBUF];
    #pragma unroll
    for (int i = 0; i < NBUF; ++i)
        sb[i] = (unsigned int)__cvta_generic_to_shared(&sm[w][i][0]);

    // prime the pipeline: chunks 0..3 in flight
    #pragma unroll
    for (int c = 0; c < NBUF; ++c) issue_chunk(gb4 + c * C4, sb[c], lane);

    float a[5];
    float acc = 0.0f;                           // accumulated log2 scale

    #pragma unroll 1
    for (int c = 0; c < NCHUNK; ++c) {
        wait_cp<NBUF - 1>();                    // <=3 outstanding -> chunk c done
        const __half* sbuf = &sm[w][c & (NBUF - 1)][0];

        if (c == 0) {                           // init at t=0 (scaled p)
            #pragma unroll
            for (int i = 0; i < 5; ++i) {
                int s = 5 * lane + i;
                a[i]  = (s < 2) ? __half2float(sbuf[eidx[i]]) : 0.0f;
            }
            #pragma unroll
            for (int r = 1; r < CH; ++r) {
                step_row(sbuf + r * GW, eidx, skipm, a, lane);
                if ((r & 7) == 7) renorm(a, acc);
            }
        } else {
            #pragma unroll
            for (int r = 0; r < CH; ++r) {
                step_row(sbuf + r * GW, eidx, skipm, a, lane);
                if ((r & 7) == 7) renorm(a, acc);
            }
        }

        if (c + NBUF < NCHUNK)                  // refill this buffer slot
            issue_chunk(gb4 + (size_t)(c + NBUF) * C4,
                        sb[(c + NBUF) & (NBUF - 1)], lane);
        else
            asm volatile("cp.async.commit_group;\n" ::: "memory"); // keep count
    }

    // states 127 (i=2) and 128 (i=3) live in lane 25.
    // 256 emit factors each carried 2^20 -> subtract 20*256 from the exponent.
    if (lane == 25) {
        float s = a[2] + a[3];                  // tail sum, linear
        out[b] = -(flog2(s) + acc - 20.0f * 256.0f) * LN2F;
    }
}

// ---------------------------------------------------------------------------
extern "C" void kernel_launch(void* const* d_in, const int* in_sizes, int n_in,
                              void* d_out, int out_size) {
    // y_pred is by far the larger buffer; robust to metadata ordering.
    const float* yp;
    const int*   yt;
    if (in_sizes[0] > in_sizes[1]) {
        yp = (const float*)d_in[0];
        yt = (const int*)d_in[1];
    } else {
        yp = (const float*)d_in[1];
        yt = (const int*)d_in[0];
    }
    float* out = (float*)d_out;

    k_reduce_gather<<<(BB * TT) / 8, 256>>>(yp, yt);   // one warp per (b,t) row
    k_alpha<<<BB / 4, 128>>>(yt, out);                 // one warp per batch
}

// round 13
// speedup vs baseline: 1.7447x; 1.1324x over previous
#include <cuda_runtime.h>
#include <cuda_fp16.h>
#include <cstdint>

#define BB 256
#define TT 256
#define CC 1024
#define LL 64
#define SS 129          // 2L+1
#define GW 80           // emit width (halves): 64 labels + blank@64 + pad
#define CH 16           // time-rows per chunk; 16*80*2B = 2560B = 5 f4/lane
#define NCHUNK (TT / CH)                // 16
#define NBUF 4                          // cp.async pipeline depth
#define EPSF 1e-7f
#define LN2F 0.69314718055994530942f
#define PSCALE 1048576.0f               // 2^20: lifts p into fp16 normal range

// scratch (no allocation allowed -> __device__ global)
__device__ __align__(16) __half g_buf[(size_t)BB * TT * GW];  // p * 2^20, fp16

__device__ __forceinline__ float flog2(float x) {
    float y; asm("lg2.approx.ftz.f32 %0, %1;" : "=f"(y) : "f"(x)); return y;
}
__device__ __forceinline__ bool detect_i64(const int* yt, int lane) {
    return __all_sync(0xffffffffu, yt[2 * lane + 1] == 0);
}
__device__ __forceinline__ int load_lab(const int* yt, bool is64, int idx) {
    int v = is64 ? yt[2 * idx] : yt[idx];
    return min(max(v, 0), CC - 1);              // clamp: safety net
}

// ---------------------------------------------------------------------------
// Kernel 1: per (b,t) row, one warp each.  ORDERING EXPERIMENT: warps walk
// rows as (t-chunk of 64, b, t-within) -- 64 consecutive warps read 256KB
// contiguous -- to test whether t-chunked production can sustain HBM rate
// (prerequisite for producer/consumer overlap next round).
// softmax(log(y+EPS)) = (y+EPS)/sum(y+EPS): one plain sum + divide.
// ---------------------------------------------------------------------------
__global__ void k_reduce_gather(const float* __restrict__ yp,
                                const int*   __restrict__ yt) {
    int W    = (blockIdx.x * blockDim.x + threadIdx.x) >> 5;
    int lane = threadIdx.x & 31;
    if (W >= BB * TT) return;
    // decode (c, b, tt): c = 64-t chunk, b = batch, tt = t within chunk
    int t = ((W >> 14) << 6) | (W & 63);
    int b = (W >> 6) & (BB - 1);
    size_t rowi = (size_t)b * TT + t;

    bool is64 = detect_i64(yt, lane);

    const float*  row  = yp + rowi * CC;
    const float4* row4 = (const float4*)row;

    float s = 0.f;
    #pragma unroll
    for (int k = 0; k < 8; ++k) {               // 8 coalesced float4 per lane
        float4 v = row4[lane + 32 * k];
        s += (v.x + v.y) + (v.z + v.w);
    }
    #pragma unroll
    for (int o = 16; o; o >>= 1) s += __shfl_xor_sync(0xffffffffu, s, o);

    float invZ = PSCALE / (s + (float)CC * EPSF);   // fold 2^20 into divide

    int lab0 = load_lab(yt, is64, b * LL + 2 * lane);
    int lab1 = load_lab(yt, is64, b * LL + 2 * lane + 1);
    __half2 v01 = __floats2half2_rn((row[lab0] + EPSF) * invZ,
                                    (row[lab1] + EPSF) * invZ);

    __half2* go2 = (__half2*)(g_buf + rowi * GW);
    go2[lane] = v01;                            // labels 2*lane, 2*lane+1
    if (lane < 8) {                             // j = 64..79: blank + zero pad
        __half2 z = __floats2half2_rn(
            (lane == 0) ? (row[CC - 1] + EPSF) * invZ : 0.f, 0.f);
        go2[32 + lane] = z;
    }
}

// ---------------------------------------------------------------------------
// Kernel 2: alpha recursion, LINEAR domain: a_new = (a1 + a2 + skip*a3) * p.
// One warp per batch, 5 states/thread, 2 shuffles/step, 4-deep cp.async
// pipeline.  Blank states share ONE broadcast LDS per row; only label states
// do individual (predicated) loads.  Renorm every 8 steps via redux.sync.
// ---------------------------------------------------------------------------
__device__ __forceinline__ void issue_chunk(const float4* gsrc,
                                            unsigned int sdst, int lane) {
    #pragma unroll
    for (int k = 0; k < (CH * GW * 2) / (16 * 32); ++k) {   // 5 iters
        int i4 = lane + 32 * k;
        asm volatile("cp.async.ca.shared.global [%0], [%1], 16;\n"
                     :: "r"(sdst + 16u * i4), "l"(gsrc + i4));
    }
    asm volatile("cp.async.commit_group;\n" ::: "memory");
}
template <int N>
__device__ __forceinline__ void wait_cp() {
    asm volatile("cp.async.wait_group %0;\n" :: "n"(N) : "memory");
    __syncwarp();
}

__device__ __forceinline__ void step_row(const __half* __restrict__ srow,
                                         const bool* __restrict__ islab,
                                         const int* __restrict__ lidx,
                                         const float* __restrict__ skipm,
                                         float* __restrict__ a, int lane) {
    float pb = __half2float(srow[64]);          // blank: one broadcast LDS
    float p[5];
    #pragma unroll
    for (int i = 0; i < 5; ++i)
        p[i] = islab[i] ? __half2float(srow[lidx[i]]) : pb;

    float q4 = __shfl_up_sync(0xffffffffu, a[4], 1);   // state 5*lane-1
    float q3 = __shfl_up_sync(0xffffffffu, a[3], 1);   // state 5*lane-2
    if (lane == 0) { q4 = 0.0f; q3 = 0.0f; }

    float n0 = (a[0] + q4   + skipm[0] * q3  ) * p[0];
    float n1 = (a[1] + a[0] + skipm[1] * q4  ) * p[1];
    float n2 = (a[2] + a[1] + skipm[2] * a[0]) * p[2];
    float n3 = (a[3] + a[2] + skipm[3] * a[1]) * p[3];
    float n4 = (a[4] + a[3] + skipm[4] * a[2]) * p[4];
    a[0] = n0; a[1] = n1; a[2] = n2; a[3] = n3; a[4] = n4;
}

__device__ __forceinline__ void renorm(float* __restrict__ a, float& acc) {
    float m = fmaxf(fmaxf(fmaxf(a[0], a[1]), fmaxf(a[2], a[3])), a[4]);
    unsigned int mu = __float_as_uint(m);       // positive floats: order-safe
    asm("redux.sync.max.u32 %0, %1, 0xffffffff;" : "=r"(mu) : "r"(mu));
    int ebits = (int)((mu >> 23) & 0xFFu);
    float scale = __int_as_float((254 - ebits) << 23);  // 2^-(e-127)
    acc += (float)(ebits - 127);
    #pragma unroll
    for (int i = 0; i < 5; ++i) a[i] *= scale;
}

__global__ void __launch_bounds__(128, 1)
k_alpha(const int* __restrict__ yt, float* __restrict__ out) {
    __shared__ __align__(16) __half sm[4][NBUF][CH * GW];  // 40,960 B

    int w    = threadIdx.x >> 5;
    int b    = blockIdx.x * 4 + w;
    int lane = threadIdx.x & 31;
    if (b >= BB) return;

    bool is64 = detect_i64(yt, lane);

    bool  islab[5];
    int   lidx[5];
    float skipm[5];
    #pragma unroll
    for (int i = 0; i < 5; ++i) {
        int s    = 5 * lane + i;
        bool odd = (s & 1);
        // valid blank -> shared pb; label -> own slot; invalid -> slot 66 (0)
        islab[i] = odd || (s >= SS);
        lidx[i]  = (odd && s < SS) ? ((s - 1) >> 1) : 66;
        skipm[i] = 0.0f;
        if (s < SS && odd && s >= 3) {          // pos>=2 and label state
            int j = (s - 1) >> 1;               // j >= 1 here
            skipm[i] = (load_lab(yt, is64, b * LL + j) !=
                        load_lab(yt, is64, b * LL + j - 1)) ? 1.0f : 0.0f;
        }
    }

    const float4* gb4 = (const float4*)(g_buf + (size_t)b * TT * GW);
    const int C4 = (CH * GW * 2) / 16;          // float4 per chunk = 160
    unsigned int sb[NBUF];
    #pragma unroll
    for (int i = 0; i < NBUF; ++i)
        sb[i] = (unsigned int)__cvta_generic_to_shared(&sm[w][i][0]);

    // prime the pipeline: chunks 0..3 in flight
    #pragma unroll
    for (int c = 0; c < NBUF; ++c) issue_chunk(gb4 + c * C4, sb[c], lane);

    float a[5];
    float acc = 0.0f;                           // accumulated log2 scale

    #pragma unroll 1
    for (int c = 0; c < NCHUNK; ++c) {
        wait_cp<NBUF - 1>();                    // <=3 outstanding -> chunk c done
        const __half* sbuf = &sm[w][c & (NBUF - 1)][0];

        if (c == 0) {                           // init at t=0 (scaled p)
            float pb0 = __half2float(sbuf[64]);
            #pragma unroll
            for (int i = 0; i < 5; ++i) {
                int s = 5 * lane + i;
                float pi = islab[i] ? __half2float(sbuf[lidx[i]]) : pb0;
                a[i] = (s < 2) ? pi : 0.0f;
            }
            #pragma unroll
            for (int r = 1; r < CH; ++r) {
                step_row(sbuf + r * GW, islab, lidx, skipm, a, lane);
                if ((r & 7) == 7) renorm(a, acc);
            }
        } else {
            #pragma unroll
            for (int r = 0; r < CH; ++r) {
                step_row(sbuf + r * GW, islab, lidx, skipm, a, lane);
                if ((r & 7) == 7) renorm(a, acc);
            }
        }

        if (c + NBUF < NCHUNK)                  // refill this buffer slot
            issue_chunk(gb4 + (size_t)(c + NBUF) * C4,
                        sb[(c + NBUF) & (NBUF - 1)], lane);
        else
            asm volatile("cp.async.commit_group;\n" ::: "memory"); // keep count
    }

    // states 127 (i=2) and 128 (i=3) live in lane 25.
    // 256 emit factors each carried 2^20 -> subtract 20*256 from the exponent.
    if (lane == 25) {
        float s = a[2] + a[3];                  // tail sum, linear
        out[b] = -(flog2(s) + acc - 20.0f * 256.0f) * LN2F;
    }
}

// ---------------------------------------------------------------------------
extern "C" void kernel_launch(void* const* d_in, const int* in_sizes, int n_in,
                              void* d_out, int out_size) {
    // y_pred is by far the larger buffer; robust to metadata ordering.
    const float* yp;
    const int*   yt;
    if (in_sizes[0] > in_sizes[1]) {
        yp = (const float*)d_in[0];
        yt = (const int*)d_in[1];
    } else {
        yp = (const float*)d_in[1];
        yt = (const int*)d_in[0];
    }
    float* out = (float*)d_out;

    k_reduce_gather<<<(BB * TT) / 8, 256>>>(yp, yt);   // one warp per (b,t) row
    k_alpha<<<BB / 4, 128>>>(yt, out);                 // one warp per batch
}